// round 11
// baseline (speedup 1.0000x reference)
#include <cuda_runtime.h>
#include <cuda_bf16.h>
#include <cstdint>
#include <cfloat>

#define D 64
#define K 512
#define MT 128        // pixels per block
#define XPAD 65       // xsm row stride (floats), conflict-free
#define XBW 36        // xbf row stride in u32 words (72 bf16) — conflict-free frag loads
#define WSW 36        // ws row stride in u32 words
#define NPIX 131072   // 32*64*64
#define HW 4096       // 64*64
#define CHW 262144    // 64*4096
#define NBLK (NPIX / MT)
#define CAP 8

__device__ float g_wnorm[K];   // C_k = ||w_k||^2
__device__ float g_bsum[NBLK];

// C_k = ||w_k||^2, sequential d-order fp32 (matches rescore rounding model)
__global__ void wnorm_kernel(const float* __restrict__ w) {
    int k = threadIdx.x;
    float s = 0.f;
#pragma unroll
    for (int i = 0; i < D; i++) {
        float v = w[k * D + i];
        s = __fmaf_rn(v, v, s);
    }
    g_wnorm[k] = s;
}

__device__ __forceinline__ uint32_t pack_bf16x2(float lo, float hi) {
    __nv_bfloat162 h = __float22bfloat162_rn(make_float2(lo, hi));  // .x -> low
    return *reinterpret_cast<uint32_t*>(&h);
}

__device__ __forceinline__ void mma16816(float c[4], const uint32_t a[4],
                                         uint32_t b0, uint32_t b1) {
    asm volatile(
        "mma.sync.aligned.m16n8k16.row.col.f32.bf16.bf16.f32 "
        "{%0,%1,%2,%3}, {%4,%5,%6,%7}, {%8,%9}, {%0,%1,%2,%3};"
        : "+f"(c[0]), "+f"(c[1]), "+f"(c[2]), "+f"(c[3])
        : "r"(a[0]), "r"(a[1]), "r"(a[2]), "r"(a[3]), "r"(b0), "r"(b1));
}

extern __shared__ char dyn_smem[];

__global__ __launch_bounds__(128, 1) void vq_kernel(
    const float* __restrict__ x, const float* __restrict__ w,
    float* __restrict__ out) {
    __shared__ float sC[K];
    __shared__ float sA[MT];
    __shared__ float sS[MT];
    __shared__ int sidx[MT];
    __shared__ float lred[128];

    int tid = threadIdx.x;
    int wid = tid >> 5;
    int lane = tid & 31;
    int qq = lane & 3;           // quad position
    int lr = lane >> 2;          // quad row 0..7

    float* xsm = reinterpret_cast<float*>(dyn_smem);            // [MT][XPAD] fp32 (33280 B)
    uint32_t* xbf = reinterpret_cast<uint32_t*>(dyn_smem + 33280);  // [MT][XBW] (18432 B)
    uint32_t* ws = reinterpret_cast<uint32_t*>(dyn_smem + 33280 + 18432); // [K][WSW] (73728 B)

    int p0 = blockIdx.x * MT;
    int b = p0 >> 12;
    int hw0 = p0 & (HW - 1);
    const float* xbase = x + (size_t)b * CHW + hw0;

    // C_k into smem
    for (int i = tid; i < K; i += 128) sC[i] = g_wnorm[i];

    // Stage x fp32 pixel-major (coalesced: m fast)
    for (int e = tid; e < D * MT; e += 128) {
        int d = e >> 7, m = e & 127;
        xsm[m * XPAD + d] = xbase[d * HW + m];
    }
    // Stage ws bf16 [code][dim], packed u32 pairs (coalesced float2 reads)
    {
        const float2* w2 = reinterpret_cast<const float2*>(w);
        for (int e = tid; e < K * 32; e += 128) {
            int k = e >> 5, j = e & 31;
            float2 v = w2[k * 32 + j];
            ws[k * WSW + j] = pack_bf16x2(v.x, v.y);
        }
    }
    __syncthreads();

    // Per-pixel exact A (sequential d-order fp32 FMA) + S, and xbf row (from xsm)
    {
        int m = tid;
        float A = 0.f, S = 0.f;
#pragma unroll
        for (int j = 0; j < 32; j++) {
            float f0 = xsm[m * XPAD + 2 * j];
            float f1 = xsm[m * XPAD + 2 * j + 1];
            A = __fmaf_rn(f0, f0, A);
            A = __fmaf_rn(f1, f1, A);
            S += fabsf(f0) + fabsf(f1);
            xbf[m * XBW + j] = pack_bf16x2(f0, f1);
        }
        sA[m] = A;
        sS[m] = S;
    }
    __syncthreads();

    // Preload A fragments: warp w owns pixel rows 32w..32w+31
    uint32_t afr[2][4][4];
    int rbase = 32 * wid;
#pragma unroll
    for (int mt = 0; mt < 2; mt++)
#pragma unroll
        for (int kt = 0; kt < 4; kt++) {
            int r = rbase + 16 * mt + lr;
            afr[mt][kt][0] = xbf[r * XBW + kt * 8 + qq];
            afr[mt][kt][1] = xbf[(r + 8) * XBW + kt * 8 + qq];
            afr[mt][kt][2] = xbf[r * XBW + kt * 8 + qq + 4];
            afr[mt][kt][3] = xbf[(r + 8) * XBW + kt * 8 + qq + 4];
        }

    // Per-lane rows: rl = mt*2+hi -> global row rbase + 16*mt + lr + 8*hi
    float marg[4], runmin[4];
    int cnt[4];
    int cand[4][CAP];
    float csc[4][CAP];
    int ovf = 0;
#pragma unroll
    for (int rl = 0; rl < 4; rl++) {
        int rg = rbase + 16 * (rl >> 1) + lr + 8 * (rl & 1);
        marg[rl] = sS[rg] * 6.1035156e-5f + 2e-4f;  // >= 2x one-sided bf16+rounding bound
        runmin[rl] = FLT_MAX;
        cnt[rl] = 0;
    }

#define INSERT(rl, sc, kk) do { \
    float th_ = runmin[rl] + marg[rl]; \
    if ((sc) <= th_) { \
        if (cnt[rl] == CAP) { \
            int wo_ = 0; \
            for (int ii_ = 0; ii_ < CAP; ii_++) \
                if (csc[rl][ii_] <= th_) { cand[rl][wo_] = cand[rl][ii_]; csc[rl][wo_] = csc[rl][ii_]; wo_++; } \
            cnt[rl] = wo_; \
        } \
        if (cnt[rl] < CAP) { cand[rl][cnt[rl]] = (kk); csc[rl][cnt[rl]] = (sc); cnt[rl]++; } \
        else ovf |= (1 << (rl)); \
    } \
    runmin[rl] = fminf(runmin[rl], (sc)); \
} while (0)

    // Main loop: 64 n-tiles of 8 codes
#pragma unroll 2
    for (int nt = 0; nt < 64; nt++) {
        int n = 8 * nt + lr;
        float acc[2][4] = {{0.f, 0.f, 0.f, 0.f}, {0.f, 0.f, 0.f, 0.f}};
#pragma unroll
        for (int kt = 0; kt < 4; kt++) {
            uint32_t b0 = ws[n * WSW + kt * 8 + qq];
            uint32_t b1 = ws[n * WSW + kt * 8 + qq + 4];
            mma16816(acc[0], afr[0][kt], b0, b1);
            mma16816(acc[1], afr[1][kt], b0, b1);
        }
        int k0 = 8 * nt + 2 * qq;
        float C0 = sC[k0], C1 = sC[k0 + 1];
#pragma unroll
        for (int mt = 0; mt < 2; mt++)
#pragma unroll
            for (int hi = 0; hi < 2; hi++) {
                int rl = mt * 2 + hi;
                float s0 = __fmaf_rn(-2.f, acc[mt][2 * hi + 0], C0);
                float s1 = __fmaf_rn(-2.f, acc[mt][2 * hi + 1], C1);
                INSERT(rl, s0, k0);
                INSERT(rl, s1, k0 + 1);
            }
    }

    // Finalize per row: quad min, threshold, exact rescore, quad merge
#pragma unroll
    for (int rl = 0; rl < 4; rl++) {
        int rg = rbase + 16 * (rl >> 1) + lr + 8 * (rl & 1);
        float qmin = runmin[rl];
        qmin = fminf(qmin, __shfl_xor_sync(0xffffffffu, qmin, 1));
        qmin = fminf(qmin, __shfl_xor_sync(0xffffffffu, qmin, 2));
        float thr = qmin + marg[rl];
        float A = sA[rg];
        float best = FLT_MAX;
        int bidx = 0x3fffffff;
        if (!((ovf >> rl) & 1)) {
            for (int i = 0; i < cnt[rl]; i++) {
                if (csc[rl][i] > thr) continue;
                int k = cand[rl][i];
                float dot = 0.f;
#pragma unroll
                for (int d = 0; d < D; d++)
                    dot = __fmaf_rn(xsm[rg * XPAD + d], __ldg(&w[k * D + d]), dot);
                float t1 = __fmaf_rn(-2.0f, dot, A);
                float sc = __fadd_rn(t1, sC[k]);
                if (sc < best) { best = sc; bidx = k; }  // ascending k => first-min kept
            }
        } else {
            // overflow: exact scan of this lane's 128 codes (ascending k)
            for (int i = 0; i < 128; i++) {
                int k = 8 * (i >> 1) + 2 * qq + (i & 1);
                float dot = 0.f;
#pragma unroll
                for (int d = 0; d < D; d++)
                    dot = __fmaf_rn(xsm[rg * XPAD + d], __ldg(&w[k * D + d]), dot);
                float t1 = __fmaf_rn(-2.0f, dot, A);
                float sc = __fadd_rn(t1, sC[k]);
                if (sc < best) { best = sc; bidx = k; }
            }
        }
        // quad merge with lower-index tiebreak (reference argmin = first occurrence)
#pragma unroll
        for (int off = 1; off <= 2; off <<= 1) {
            float ob = __shfl_xor_sync(0xffffffffu, best, off);
            int oi = __shfl_xor_sync(0xffffffffu, bidx, off);
            if (ob < best || (ob == best && oi < bidx)) { best = ob; bidx = oi; }
        }
        if (qq == 0) {
            sidx[rg] = bidx;
            out[p0 + rg] = (float)bidx;
        }
    }
    __syncthreads();

    // Epilogue: straight-through fl(x + fl(q-x)) + loss partial (coalesced stores)
    float lsum = 0.f;
    float* qout = out + NPIX + (size_t)b * CHW + hw0;
    for (int e = tid; e < D * MT; e += 128) {
        int d = e >> 7, mm = e & 127;
        float wv = w[sidx[mm] * D + d];
        float xv = xsm[mm * XPAD + d];
        float df = __fsub_rn(wv, xv);
        lsum = __fmaf_rn(df, df, lsum);
        qout[d * HW + mm] = __fadd_rn(xv, df);
    }
    lred[tid] = lsum;
    __syncthreads();
    for (int s = 64; s > 0; s >>= 1) {
        if (tid < s) lred[tid] += lred[tid + s];
        __syncthreads();
    }
    if (tid == 0) g_bsum[blockIdx.x] = lred[0];
}

// Deterministic fixed-order final loss reduce: loss = 1.25 * sum / (N*D)
__global__ void loss_kernel(float* __restrict__ out) {
    __shared__ float r[256];
    int tid = threadIdx.x;
    float s = 0.f;
    for (int i = tid; i < NBLK; i += 256) s += g_bsum[i];
    r[tid] = s;
    __syncthreads();
    for (int st = 128; st > 0; st >>= 1) {
        if (tid < st) r[tid] += r[tid + st];
        __syncthreads();
    }
    if (tid == 0) out[NPIX + (size_t)32 * CHW] = 1.25f * r[0] / 8388608.f;
}

extern "C" void kernel_launch(void* const* d_in, const int* in_sizes, int n_in,
                              void* d_out, int out_size) {
    const float* x = (const float*)d_in[0];   // [32, 64, 64, 64] NCHW fp32
    const float* w = (const float*)d_in[1];   // [512, 64] fp32
    float* out = (float*)d_out;

    size_t smem_bytes = 33280 + 18432 + 73728;  // xsm + xbf + ws = 125440 B
    cudaFuncSetAttribute(vq_kernel, cudaFuncAttributeMaxDynamicSharedMemorySize,
                         (int)smem_bytes);

    wnorm_kernel<<<1, K>>>(w);
    vq_kernel<<<NBLK, 128, smem_bytes>>>(x, w, out);
    loss_kernel<<<1, 256>>>(out);
}

// round 16
// speedup vs baseline: 1.2640x; 1.2640x over previous
#include <cuda_runtime.h>
#include <cstdint>
#include <cfloat>

#define D 64
#define K 512
#define MT 128          // pixels per block
#define XS_STRIDE 132   // xs row stride (floats): 16B-aligned rows, conflict-free
#define WS_STRIDE 260   // ws row stride (floats): 16B-aligned, low-conflict staging
#define NPIX 131072     // 32*64*64
#define HW 4096         // 64*64
#define CHW 262144      // 64*4096
#define NBLK (NPIX / MT)

__device__ float g_wnorm[K];   // C_k = ||w_k||^2
__device__ float g_bsum[NBLK];

// C_k = ||w_k||^2, sequential d-order fp32 (reference rounding model)
__global__ void wnorm_kernel(const float* __restrict__ w) {
    int k = threadIdx.x;  // 512 threads, 1 block
    float s = 0.f;
#pragma unroll
    for (int i = 0; i < D; i++) {
        float v = w[k * D + i];
        s = __fmaf_rn(v, v, s);
    }
    g_wnorm[k] = s;
}

// Packed dual-fp32 FMA: each half is an exact fp32 fma.rn (bit-identical to FFMA)
__device__ __forceinline__ void ffma2(unsigned long long& acc,
                                      unsigned long long a, unsigned long long b) {
    asm("fma.rn.f32x2 %0, %1, %2, %0;" : "+l"(acc) : "l"(a), "l"(b));
}
__device__ __forceinline__ float lo_f(unsigned long long v) {
    return __uint_as_float((uint32_t)v);
}
__device__ __forceinline__ float hi_f(unsigned long long v) {
    return __uint_as_float((uint32_t)(v >> 32));
}

extern __shared__ float smem_f[];

__global__ __launch_bounds__(256, 2) void vq_kernel(
    const float* __restrict__ x, const float* __restrict__ w,
    float* __restrict__ out) {
    __shared__ float sC[K];
    __shared__ float sA[MT];
    __shared__ int sidx[MT];
    __shared__ float lred[256];

    float* xs = smem_f;                       // [64][XS_STRIDE] fp32, x dim-major
    float* ws = smem_f + D * XS_STRIDE;       // [64][WS_STRIDE] duplicated w pairs

    int tid = threadIdx.x;
    int tc = tid & 15;     // code column (16 cols x 8 codes = 128 codes/chunk)
    int tr = tid >> 4;     // pixel row   (16 rows x 8 pixels = 128 pixels)
    int m0 = tr * 8;

    int p0 = blockIdx.x * MT;
    int b = p0 >> 12;      // 128 | 4096 -> one batch per block
    int hw0 = p0 & (HW - 1);
    const float* xbase = x + (size_t)b * CHW + hw0;

    // C_k into smem
    for (int i = tid; i < K; i += 256) sC[i] = g_wnorm[i];

    // Stage x: xs[d][m], coalesced gmem (m fast), conflict-free smem writes
    for (int e = tid; e < D * MT; e += 256) {
        int d = e >> 7, m = e & 127;
        xs[d * XS_STRIDE + m] = xbase[d * HW + m];
    }
    __syncthreads();

    // A_m = ||x_m||^2, sequential d-order fp32 (exact reference chain)
    if (tid < MT) {
        float s = 0.f;
#pragma unroll
        for (int d = 0; d < D; d++) {
            float v = xs[d * XS_STRIDE + tid];
            s = __fmaf_rn(v, v, s);
        }
        sA[tid] = s;
    }
    __syncthreads();

    float a[8];
#pragma unroll
    for (int i = 0; i < 8; i++) a[i] = sA[m0 + i];

    float minsc[8];
    int minidx[8];
#pragma unroll
    for (int i = 0; i < 8; i++) { minsc[i] = FLT_MAX; minidx[i] = 0; }

#pragma unroll 1
    for (int kc = 0; kc < 4; kc++) {
        __syncthreads();  // prior chunk's ws reads complete
        // Stage duplicated w pairs: ws[d][2*kk] = ws[d][2*kk+1] = w[kc*128+kk][d]
        // (d fast -> coalesced gmem; float2 store of (v,v))
        for (int e = tid; e < D * 128; e += 256) {
            int d = e & 63, kk = e >> 6;
            float v = w[(kc * 128 + kk) * D + d];
            *reinterpret_cast<float2*>(&ws[d * WS_STRIDE + 2 * kk]) = make_float2(v, v);
        }
        __syncthreads();

        unsigned long long acc[4][8];
#pragma unroll
        for (int i = 0; i < 4; i++)
#pragma unroll
            for (int j = 0; j < 8; j++) acc[i][j] = 0ULL;  // (0.0f, 0.0f)

#pragma unroll 8
        for (int d = 0; d < D; d++) {
            // 4 natural pixel pairs (lo = lower address = even pixel)
            ulonglong2 xa = *reinterpret_cast<const ulonglong2*>(&xs[d * XS_STRIDE + m0]);
            ulonglong2 xb = *reinterpret_cast<const ulonglong2*>(&xs[d * XS_STRIDE + m0 + 4]);
            // 8 duplicated code pairs (w,w)
            const float* wrow = &ws[d * WS_STRIDE + tc * 16];
            ulonglong2 w01 = *reinterpret_cast<const ulonglong2*>(wrow);
            ulonglong2 w23 = *reinterpret_cast<const ulonglong2*>(wrow + 4);
            ulonglong2 w45 = *reinterpret_cast<const ulonglong2*>(wrow + 8);
            ulonglong2 w67 = *reinterpret_cast<const ulonglong2*>(wrow + 12);
            unsigned long long xp[4] = {xa.x, xa.y, xb.x, xb.y};
            unsigned long long wd[8] = {w01.x, w01.y, w23.x, w23.y,
                                        w45.x, w45.y, w67.x, w67.y};
#pragma unroll
            for (int i = 0; i < 4; i++)
#pragma unroll
                for (int j = 0; j < 8; j++) ffma2(acc[i][j], xp[i], wd[j]);
        }

        // Exact reference-rounded scores: sc = fl( fl(A - 2*dot) + C ), first-min
#pragma unroll
        for (int j = 0; j < 8; j++) {
            int k = kc * 128 + tc * 8 + j;
            float Ck = sC[k];
#pragma unroll
            for (int i = 0; i < 4; i++) {
                float dlo = lo_f(acc[i][j]);
                float dhi = hi_f(acc[i][j]);
                float t1 = __fmaf_rn(-2.0f, dlo, a[2 * i]);
                float sc = __fadd_rn(t1, Ck);
                if (sc < minsc[2 * i]) { minsc[2 * i] = sc; minidx[2 * i] = k; }
                t1 = __fmaf_rn(-2.0f, dhi, a[2 * i + 1]);
                sc = __fadd_rn(t1, Ck);
                if (sc < minsc[2 * i + 1]) { minsc[2 * i + 1] = sc; minidx[2 * i + 1] = k; }
            }
        }
    }

    __syncthreads();
    // Cross-thread argmin reduction (reuse ws region)
    float* rsc = ws;                                     // [MT][17]
    int* rix = reinterpret_cast<int*>(ws + MT * 17);     // [MT][17]
#pragma unroll
    for (int i = 0; i < 8; i++) {
        rsc[(m0 + i) * 17 + tc] = minsc[i];
        rix[(m0 + i) * 17 + tc] = minidx[i];
    }
    __syncthreads();
    if (tid < MT) {
        float best = rsc[tid * 17];
        int bidx = rix[tid * 17];
#pragma unroll
        for (int c = 1; c < 16; c++) {
            float sc = rsc[tid * 17 + c];
            int ix = rix[tid * 17 + c];
            if (sc < best || (sc == best && ix < bidx)) { best = sc; bidx = ix; }
        }
        sidx[tid] = bidx;
        out[p0 + tid] = (float)bidx;   // discrete_latent (as float)
    }
    __syncthreads();

    // Epilogue: straight-through fl(x + fl(q-x)) + loss partial (coalesced stores)
    float lsum = 0.f;
    float* qout = out + NPIX + (size_t)b * CHW + hw0;
    for (int e = tid; e < D * MT; e += 256) {
        int d = e >> 7, m = e & 127;
        float wv = w[sidx[m] * D + d];      // scattered, L2-hot (codebook 128KB)
        float xv = xs[d * XS_STRIDE + m];
        float df = __fsub_rn(wv, xv);
        lsum = __fmaf_rn(df, df, lsum);
        qout[d * HW + m] = __fadd_rn(xv, df);
    }
    lred[tid] = lsum;
    __syncthreads();
    for (int s = 128; s > 0; s >>= 1) {
        if (tid < s) lred[tid] += lred[tid + s];
        __syncthreads();
    }
    if (tid == 0) g_bsum[blockIdx.x] = lred[0];
}

// Deterministic fixed-order final loss reduce: loss = 1.25 * sum / (N*D)
__global__ void loss_kernel(float* __restrict__ out) {
    __shared__ float r[256];
    int tid = threadIdx.x;
    float s = 0.f;
    for (int i = tid; i < NBLK; i += 256) s += g_bsum[i];
    r[tid] = s;
    __syncthreads();
    for (int st = 128; st > 0; st >>= 1) {
        if (tid < st) r[tid] += r[tid + st];
        __syncthreads();
    }
    if (tid == 0) out[NPIX + (size_t)32 * CHW] = 1.25f * r[0] / 8388608.f;
}

extern "C" void kernel_launch(void* const* d_in, const int* in_sizes, int n_in,
                              void* d_out, int out_size) {
    const float* x = (const float*)d_in[0];   // [32, 64, 64, 64] NCHW fp32
    const float* w = (const float*)d_in[1];   // [512, 64] fp32
    float* out = (float*)d_out;

    size_t smem_bytes = (size_t)(D * XS_STRIDE + D * WS_STRIDE) * sizeof(float); // 100352 B
    cudaFuncSetAttribute(vq_kernel, cudaFuncAttributeMaxDynamicSharedMemorySize,
                         (int)smem_bytes);

    wnorm_kernel<<<1, K>>>(w);
    vq_kernel<<<NBLK, 256, smem_bytes>>>(x, w, out);
    loss_kernel<<<1, 256>>>(out);
}